// round 4
// baseline (speedup 1.0000x reference)
#include <cuda_runtime.h>

// ---------------------------------------------------------------------------
// SLAYER SNN forward on GB300:
// pool4 -> psp -> conv5x5(2->32) -> psp -> pool2 -> psp -> conv3x3(32->64)
// -> psp -> pool2 -> psp -> conv3x3(64->64) -> psp -> fc(4096->256) -> psp
// -> fc(256->11) -> psp.   N=4, T=300, fp32 throughout.
// ---------------------------------------------------------------------------

#define T 300
#define NB 4

// psp constants (float-rounded values of the f32 reference constants)
#define A_SR 0.90483741803595957f   // exp(-1/10)
#define A_RF 0.36787944117144233f   // exp(-1)
#define C_SR 0.27182818284590452f   // e/10
#define C_RF -54.365636569180902f   // -2*10*e
#define THETA 10.0f

// ---------------- scratch offsets (floats) ----------------
static const size_t OFF_P0 = 0;          //  4*2*32*32*300
static const size_t OFF_S0 = 2457600;
static const size_t OFF_A1 = 4915200;    //  4*32*32*32*300
static const size_t OFF_S1 = 44236800;
static const size_t OFF_A2 = 83558400;   //  4*32*16*16*300
static const size_t OFF_S2 = 93388800;
static const size_t OFF_A3 = 103219200;  //  4*64*16*16*300
static const size_t OFF_S3 = 122880000;
static const size_t OFF_A4 = 142540800;  //  4*64*8*8*300
static const size_t OFF_S4 = 147456000;
static const size_t OFF_A5 = 152371200;  //  4*64*8*8*300
static const size_t OFF_S5 = 157286400;
static const size_t OFF_A6 = 162201600;  //  4*256*300
static const size_t OFF_S6 = 162508800;
static const size_t OFF_A7 = 162816000;  //  4*11*300
// total = 162829200 floats = 651.3 MB

__device__ float g_buf[162829200];

// ---------------- sum pool (x 1.1*theta) ----------------
template<int K>
__global__ __launch_bounds__(128) void pool_kernel(
    const float* __restrict__ src, float* __restrict__ dst,
    int C, int HO, int WO)
{
    int idx = blockIdx.x;                 // n*C*HO*WO
    int x = idx % WO; int r = idx / WO;
    int y = r % HO;   r /= HO;
    int c = r % C;    int n = r / C;
    const int WI = WO * K;
    const int HI = HO * K;
    const float* sp = src + (((((size_t)n * C + c) * HI + (size_t)y * K) * WI) + (size_t)x * K) * T;
    float* dp = dst + (size_t)idx * T;
    for (int t = threadIdx.x; t < T; t += 128) {
        float s = 0.f;
        #pragma unroll
        for (int i = 0; i < K; i++)
            #pragma unroll
            for (int j = 0; j < K; j++)
                s += sp[((size_t)i * WI + j) * T + t];
        dp[t] = 11.0f * s;
    }
}

// ---------------- psp + spike (2-state IIR, sequential in t) ----------------
// Warp owns 32 neurons; 32x32 (neuron x t) tiles through smem -> coalesced.
__global__ __launch_bounds__(128) void psp_kernel(
    const float* __restrict__ src, float* __restrict__ dst, int nNeurons)
{
    __shared__ float buf[4][32][33];
    const int warp = threadIdx.x >> 5, lane = threadIdx.x & 31;
    const int base = (blockIdx.x * 4 + warp) * 32;
    if (base >= nNeurons) return;

    float gp = 0.f, hp = 0.f, gr = 0.f, hr = 0.f;

    for (int tt = 0; tt < T; tt += 32) {
        const int tl = (T - tt < 32) ? (T - tt) : 32;
        #pragma unroll 4
        for (int j = 0; j < 32; j++) {
            int ni = base + j;
            float v = 0.f;
            if (ni < nNeurons && lane < tl)
                v = src[(size_t)ni * T + tt + lane];
            buf[warp][j][lane] = v;
        }
        __syncwarp();
        for (int k = 0; k < tl; k++) {
            float xi = buf[warp][lane][k];
            hp = __fmul_rn(A_SR, __fadd_rn(hp, gp));
            gp = __fadd_rn(__fmul_rn(A_SR, gp), xi);
            hr = __fmul_rn(A_RF, __fadd_rn(hr, gr));
            gr = __fmul_rn(A_RF, gr);
            float u = __fadd_rn(__fmul_rn(C_SR, hp), __fmul_rn(C_RF, hr));
            float s = (u >= THETA) ? 1.0f : 0.0f;
            gr = __fadd_rn(gr, s);
            buf[warp][lane][k] = s;
        }
        __syncwarp();
        #pragma unroll 4
        for (int j = 0; j < 32; j++) {
            int ni = base + j;
            if (ni < nNeurons && lane < tl)
                dst[(size_t)ni * T + tt + lane] = buf[warp][j][lane];
        }
        __syncwarp();
    }
}

// ---------------- per-timestep 2D conv ----------------
// grid: (H*W, OC/G, N); block: 128 threads over t; G oc per thread in regs.
template<int IC, int K, int PAD, int G>
__global__ __launch_bounds__(128) void conv_kernel(
    const float* __restrict__ src, float* __restrict__ dst,
    const float* __restrict__ w, int H, int W)
{
    __shared__ float sw[G * IC * K * K];
    const int xy = blockIdx.x;
    const int x = xy % W, y = xy / W;
    const int og = blockIdx.y;
    const int n  = blockIdx.z;
    const int OC = gridDim.y * G;
    const int ICKK = IC * K * K;

    for (int i = threadIdx.x; i < G * ICKK; i += 128)
        sw[i] = w[(size_t)og * G * ICKK + i];
    __syncthreads();

    const float* sb = src + (size_t)n * IC * H * W * T;
    for (int t = threadIdx.x; t < T; t += 128) {
        float acc[G];
        #pragma unroll
        for (int g = 0; g < G; g++) acc[g] = 0.f;
        #pragma unroll
        for (int ky = 0; ky < K; ky++) {
            int iy = y + ky - PAD;
            if (iy < 0 || iy >= H) continue;
            #pragma unroll
            for (int kx = 0; kx < K; kx++) {
                int ix = x + kx - PAD;
                if (ix < 0 || ix >= W) continue;
                #pragma unroll 4
                for (int ic = 0; ic < IC; ic++) {
                    float v = sb[((size_t)(ic * H + iy) * W + ix) * T + t];
                    const float* wp = &sw[ic * K * K + ky * K + kx];
                    #pragma unroll
                    for (int g = 0; g < G; g++)
                        acc[g] += v * wp[(size_t)g * ICKK];
                }
            }
        }
        float* dp = dst + (((size_t)(n * OC + og * G) * H + y) * W + x) * T + t;
        #pragma unroll
        for (int g = 0; g < G; g++)
            dp[(size_t)g * H * W * T] = acc[g];
    }
}

// ---------------- fully connected over features, t parallel ----------------
// grid: (OC/G, N); block 128 over t (each thread: up to 3 t values).
template<int G, int CF>
__global__ __launch_bounds__(128) void fc_kernel(
    const float* __restrict__ src, float* __restrict__ dst,
    const float* __restrict__ w, int INF, int OC)
{
    __shared__ float sw[G * CF];
    const int og = blockIdx.x;
    const int n  = blockIdx.y;

    float acc[3][G];
    #pragma unroll
    for (int tc = 0; tc < 3; tc++)
        #pragma unroll
        for (int g = 0; g < G; g++) acc[tc][g] = 0.f;

    for (int f0 = 0; f0 < INF; f0 += CF) {
        __syncthreads();
        for (int i = threadIdx.x; i < G * CF; i += 128) {
            int g = i / CF, f = i % CF;
            sw[i] = w[(size_t)(og * G + g) * INF + f0 + f];
        }
        __syncthreads();
        for (int f = 0; f < CF; f++) {
            #pragma unroll
            for (int tc = 0; tc < 3; tc++) {
                int t = tc * 128 + threadIdx.x;
                if (t < T) {
                    float v = src[((size_t)n * INF + f0 + f) * T + t];
                    #pragma unroll
                    for (int g = 0; g < G; g++)
                        acc[tc][g] += v * sw[g * CF + f];
                }
            }
        }
    }
    #pragma unroll
    for (int tc = 0; tc < 3; tc++) {
        int t = tc * 128 + threadIdx.x;
        if (t < T) {
            #pragma unroll
            for (int g = 0; g < G; g++)
                dst[(size_t)(n * OC + og * G + g) * T + t] = acc[tc][g];
        }
    }
}

// ---------------------------------------------------------------------------
extern "C" void kernel_launch(void* const* d_in, const int* in_sizes, int n_in,
                              void* d_out, int out_size)
{
    const float* s_in = (const float*)d_in[0];   // (4,2,128,128,300)
    const float* w1   = (const float*)d_in[1];   // (32,2,5,5)
    const float* w2   = (const float*)d_in[2];   // (64,32,3,3)
    const float* w3   = (const float*)d_in[3];   // (64,64,3,3)
    const float* w4a  = (const float*)d_in[4];   // (256,4096)
    const float* w4b  = (const float*)d_in[5];   // (11,256)
    float* out = (float*)d_out;                  // (4,11,300)

    float* buf = nullptr;
    cudaGetSymbolAddress((void**)&buf, g_buf);

    float* P0 = buf + OFF_P0; float* S0 = buf + OFF_S0;
    float* A1 = buf + OFF_A1; float* S1 = buf + OFF_S1;
    float* A2 = buf + OFF_A2; float* S2 = buf + OFF_S2;
    float* A3 = buf + OFF_A3; float* S3 = buf + OFF_S3;
    float* A4 = buf + OFF_A4; float* S4 = buf + OFF_S4;
    float* A5 = buf + OFF_A5; float* S5 = buf + OFF_S5;
    float* A6 = buf + OFF_A6; float* S6 = buf + OFF_S6;
    float* A7 = buf + OFF_A7;

    // L0: pool4 (4,2,128,128)->(4,2,32,32), psp
    pool_kernel<4><<<NB * 2 * 32 * 32, 128>>>(s_in, P0, 2, 32, 32);
    psp_kernel<<<(NB * 2 * 32 * 32 + 127) / 128, 128>>>(P0, S0, NB * 2 * 32 * 32);

    // L1: conv 5x5, 2->32, pad2, psp
    conv_kernel<2, 5, 2, 16><<<dim3(32 * 32, 2, NB), 128>>>(S0, A1, w1, 32, 32);
    psp_kernel<<<(NB * 32 * 32 * 32 + 127) / 128, 128>>>(A1, S1, NB * 32 * 32 * 32);

    // L2: pool2 -> (4,32,16,16), psp
    pool_kernel<2><<<NB * 32 * 16 * 16, 128>>>(S1, A2, 32, 16, 16);
    psp_kernel<<<(NB * 32 * 16 * 16 + 127) / 128, 128>>>(A2, S2, NB * 32 * 16 * 16);

    // L3: conv 3x3, 32->64, pad1, psp
    conv_kernel<32, 3, 1, 16><<<dim3(16 * 16, 4, NB), 128>>>(S2, A3, w2, 16, 16);
    psp_kernel<<<(NB * 64 * 16 * 16 + 127) / 128, 128>>>(A3, S3, NB * 64 * 16 * 16);

    // L4: pool2 -> (4,64,8,8), psp
    pool_kernel<2><<<NB * 64 * 8 * 8, 128>>>(S3, A4, 64, 8, 8);
    psp_kernel<<<(NB * 64 * 8 * 8 + 127) / 128, 128>>>(A4, S4, NB * 64 * 8 * 8);

    // L5: conv 3x3, 64->64, pad1, psp
    conv_kernel<64, 3, 1, 16><<<dim3(8 * 8, 4, NB), 128>>>(S4, A5, w3, 8, 8);
    psp_kernel<<<(NB * 64 * 8 * 8 + 127) / 128, 128>>>(A5, S5, NB * 64 * 8 * 8);

    // L6: fc 4096->256, psp
    fc_kernel<16, 256><<<dim3(16, NB), 128>>>(S5, A6, w4a, 4096, 256);
    psp_kernel<<<(NB * 256 + 127) / 128, 128>>>(A6, S6, NB * 256);

    // L7: fc 256->11, psp -> out
    fc_kernel<11, 256><<<dim3(1, NB), 128>>>(S6, A7, w4b, 256, 11);
    psp_kernel<<<1, 128>>>(A7, out, NB * 11);
}

// round 6
// speedup vs baseline: 2.1463x; 2.1463x over previous
#include <cuda_runtime.h>

// ---------------------------------------------------------------------------
// SLAYER SNN forward on GB300 (sm_103a), fp32, exact-order FMAs.
// pool4 -> psp -> conv5x5(2->32) -> psp -> pool2 -> psp -> conv3x3(32->64)
// -> psp -> pool2 -> psp -> conv3x3(64->64) -> psp -> fc(4096->256) -> psp
// -> fc(256->11) -> psp.   N=4, T=300 (internal stride TP=320).
// Compute kernels use fma.rn.f32x2 (packed fp32 FMA, 2 MAC/slot).
// ---------------------------------------------------------------------------

#define T  300
#define TP 320
#define NB 4

// psp constants (f32-rounded reference constants)
#define A_SR 0.90483741803595957f   // exp(-1/10)
#define A_RF 0.36787944117144233f   // exp(-1)
#define C_SR 0.27182818284590452f   // e/10
#define C_RF -54.365636569180902f   // -2*10*e
#define THETA 10.0f

typedef unsigned long long u64;

// ---------------- scratch offsets (floats), stride TP ----------------
static const size_t OFF_P0 = 0;          // 4*2*32*32*320   = 2,621,440
static const size_t OFF_S0 = 2621440;
static const size_t OFF_A1 = 5242880;    // 4*32*32*32*320  = 41,943,040
static const size_t OFF_S1 = 47185920;
static const size_t OFF_A2 = 89128960;   // 4*32*16*16*320  = 10,485,760
static const size_t OFF_S2 = 99614720;
static const size_t OFF_A3 = 110100480;  // 4*64*16*16*320  = 20,971,520
static const size_t OFF_S3 = 131072000;
static const size_t OFF_A4 = 152043520;  // 4*64*8*8*320    = 5,242,880
static const size_t OFF_S4 = 157286400;
static const size_t OFF_A5 = 162529280;
static const size_t OFF_S5 = 167772160;
static const size_t OFF_A6 = 173015040;  // 4*256*320       = 327,680
static const size_t OFF_S6 = 173342720;
static const size_t OFF_A7 = 173670400;  // 4*11*320        = 14,080
// total = 173,684,480 floats = 694.7 MB

__device__ float g_buf[173684480];

// ---------------- f32x2 helpers ----------------
__device__ __forceinline__ u64 pack2(float a, float b) {
    u64 r; asm("mov.b64 %0, {%1, %2};" : "=l"(r) : "f"(a), "f"(b)); return r;
}
__device__ __forceinline__ void fma2(u64 &d, u64 a, u64 b) {
    asm("fma.rn.f32x2 %0, %1, %2, %0;" : "+l"(d) : "l"(a), "l"(b));
}

// ---------------- sum pool (x 1.1*theta), float2 vectorized ----------------
// grid: n*C*HO*WO blocks; 160 threads, thread tid handles t = {2tid, 2tid+1}.
template<int K>
__global__ __launch_bounds__(160) void pool_kernel(
    const float* __restrict__ src, float* __restrict__ dst,
    int C, int HO, int WO, int srcStride)
{
    int idx = blockIdx.x;
    int x = idx % WO; int r = idx / WO;
    int y = r % HO;   r /= HO;
    int c = r % C;    int n = r / C;
    const int WI = WO * K;
    const int HI = HO * K;
    const int t = threadIdx.x * 2;
    if (t >= T) return;
    const float* sp = src + (((((size_t)n * C + c) * HI + (size_t)y * K) * WI)
                             + (size_t)x * K) * srcStride + t;
    float sa = 0.f, sb = 0.f;
    #pragma unroll
    for (int i = 0; i < K; i++)
        #pragma unroll
        for (int j = 0; j < K; j++) {
            float2 v = *(const float2*)(sp + ((size_t)i * WI + j) * srcStride);
            sa += v.x; sb += v.y;
        }
    float2 o; o.x = 11.0f * sa; o.y = 11.0f * sb;
    *(float2*)(dst + (size_t)idx * TP + t) = o;
}

// ---------------- psp + spike (2-state IIR, sequential in t) ----------------
// Warp owns 32 neurons; 32x32 (neuron x t) smem tiles -> coalesced global IO.
// dstStride doubles as the write bound: 320 => zero-pad t in [300,320);
// 300 (final output) => write only t<300.
__global__ __launch_bounds__(128) void psp_kernel(
    const float* __restrict__ src, float* __restrict__ dst,
    int nNeurons, int dstStride)
{
    __shared__ float buf[4][32][33];
    const int warp = threadIdx.x >> 5, lane = threadIdx.x & 31;
    const int base = (blockIdx.x * 4 + warp) * 32;
    if (base >= nNeurons) return;

    float gp = 0.f, hp = 0.f, gr = 0.f, hr = 0.f;

    for (int tt = 0; tt < TP; tt += 32) {
        // load tile (zeros beyond T)
        #pragma unroll 4
        for (int j = 0; j < 32; j++) {
            int ni = base + j;
            float v = 0.f;
            if (ni < nNeurons && tt + lane < T)
                v = src[(size_t)ni * TP + tt + lane];
            buf[warp][j][lane] = v;
        }
        __syncwarp();
        // sequential recursion over this tile (lane = neuron)
        #pragma unroll 4
        for (int k = 0; k < 32; k++) {
            float s;
            if (tt + k < T) {
                float xi = buf[warp][lane][k];
                hp = __fmul_rn(A_SR, __fadd_rn(hp, gp));
                gp = __fadd_rn(__fmul_rn(A_SR, gp), xi);
                hr = __fmul_rn(A_RF, __fadd_rn(hr, gr));
                gr = __fmul_rn(A_RF, gr);
                float u = __fadd_rn(__fmul_rn(C_SR, hp), __fmul_rn(C_RF, hr));
                s = (u >= THETA) ? 1.0f : 0.0f;
                gr = __fadd_rn(gr, s);
            } else {
                s = 0.f;  // zero padding
            }
            buf[warp][lane][k] = s;
        }
        __syncwarp();
        // store tile
        #pragma unroll 4
        for (int j = 0; j < 32; j++) {
            int ni = base + j;
            if (ni < nNeurons && tt + lane < dstStride)
                dst[(size_t)ni * dstStride + tt + lane] = buf[warp][j][lane];
        }
        __syncwarp();
    }
}

// ---------------- per-timestep 2D conv, f32x2 packed ----------------
// grid: (H*W/4, OC/G, N); block 128 = 4 warps, warp -> one pixel.
// lane covers t = 2*lane + 64*j, j=0..4 (TP=320). G oc accumulated in regs.
// Weights duplicated to (w,w) u64 pairs in smem.
template<int IC, int K, int PAD, int G>
__global__ __launch_bounds__(128) void conv_kernel(
    const float* __restrict__ src, float* __restrict__ dst,
    const float* __restrict__ w, int H, int W)
{
    constexpr int KK = K * K;
    constexpr int ICKK = IC * KK;
    __shared__ u64 swd[G * ICKK];

    const int lane = threadIdx.x & 31;
    const int warp = threadIdx.x >> 5;
    const int og = blockIdx.y;
    const int n  = blockIdx.z;
    const int OC = gridDim.y * G;

    for (int i = threadIdx.x; i < G * ICKK; i += 128) {
        float v = w[(size_t)og * G * ICKK + i];
        swd[i] = pack2(v, v);
    }
    __syncthreads();

    const int pixel = blockIdx.x * 4 + warp;
    const int x = pixel % W, y = pixel / W;

    u64 acc[5][G];
    #pragma unroll
    for (int j = 0; j < 5; j++)
        #pragma unroll
        for (int g = 0; g < G; g++) acc[j][g] = 0ull;

    const float* sb = src + ((size_t)n * IC * H * W) * TP + lane * 2;

    #pragma unroll
    for (int ky = 0; ky < K; ky++) {
        int iy = y + ky - PAD;
        if (iy < 0 || iy >= H) continue;
        #pragma unroll
        for (int kx = 0; kx < K; kx++) {
            int ix = x + kx - PAD;
            if (ix < 0 || ix >= W) continue;
            const float* tap = sb + (size_t)(iy * W + ix) * TP;
            #pragma unroll (IC <= 4 ? IC : 2)
            for (int ic = 0; ic < IC; ic++) {
                const float* p = tap + (size_t)ic * H * W * TP;
                u64 v[5];
                #pragma unroll
                for (int j = 0; j < 5; j++)
                    v[j] = *(const u64*)(p + 64 * j);
                #pragma unroll
                for (int g = 0; g < G; g++) {
                    u64 wv = swd[g * ICKK + ic * KK + ky * K + kx];
                    #pragma unroll
                    for (int j = 0; j < 5; j++)
                        fma2(acc[j][g], v[j], wv);
                }
            }
        }
    }

    float* dp = dst + ((size_t)(n * OC + og * G) * H * W + pixel) * TP + lane * 2;
    #pragma unroll
    for (int g = 0; g < G; g++)
        #pragma unroll
        for (int j = 0; j < 5; j++)
            *(u64*)(dp + (size_t)g * H * W * TP + 64 * j) = acc[j][g];
}

// ---------------- fully connected, f32x2 packed ----------------
// grid: (OC/G, N); block 160 = 5 warps, warp -> 64-t chunk (lane: t=2*lane+64*warp).
// Features staged through smem in CF chunks, consumed in flat f order
// (preserves reference summation order exactly).
template<int G, int CF>
__global__ __launch_bounds__(160) void fc_kernel(
    const float* __restrict__ src, float* __restrict__ dst,
    const float* __restrict__ w, int INF, int OC)
{
    __shared__ u64 swd[G * CF];
    const int lane = threadIdx.x & 31, warp = threadIdx.x >> 5;
    const int og = blockIdx.x, n = blockIdx.y;
    const int tbase = warp * 64 + lane * 2;

    u64 acc[G];
    #pragma unroll
    for (int g = 0; g < G; g++) acc[g] = 0ull;

    for (int f0 = 0; f0 < INF; f0 += CF) {
        __syncthreads();
        for (int i = threadIdx.x; i < G * CF; i += 160) {
            float v = w[(size_t)(og * G + i / CF) * INF + f0 + (i % CF)];
            swd[i] = pack2(v, v);
        }
        __syncthreads();
        const float* sp = src + ((size_t)n * INF + f0) * TP + tbase;
        for (int f = 0; f < CF; f++) {
            u64 v = *(const u64*)(sp + (size_t)f * TP);
            #pragma unroll
            for (int g = 0; g < G; g++)
                fma2(acc[g], v, swd[g * CF + f]);
        }
    }

    float* dp = dst + ((size_t)n * OC + og * G) * TP + tbase;
    #pragma unroll
    for (int g = 0; g < G; g++)
        *(u64*)(dp + (size_t)g * TP) = acc[g];
}

// ---------------------------------------------------------------------------
extern "C" void kernel_launch(void* const* d_in, const int* in_sizes, int n_in,
                              void* d_out, int out_size)
{
    const float* s_in = (const float*)d_in[0];   // (4,2,128,128,300)
    const float* w1   = (const float*)d_in[1];   // (32,2,5,5)
    const float* w2   = (const float*)d_in[2];   // (64,32,3,3)
    const float* w3   = (const float*)d_in[3];   // (64,64,3,3)
    const float* w4a  = (const float*)d_in[4];   // (256,4096)
    const float* w4b  = (const float*)d_in[5];   // (11,256)
    float* out = (float*)d_out;                  // (4,11,300)

    float* buf = nullptr;
    cudaGetSymbolAddress((void**)&buf, g_buf);

    float* P0 = buf + OFF_P0; float* S0 = buf + OFF_S0;
    float* A1 = buf + OFF_A1; float* S1 = buf + OFF_S1;
    float* A2 = buf + OFF_A2; float* S2 = buf + OFF_S2;
    float* A3 = buf + OFF_A3; float* S3 = buf + OFF_S3;
    float* A4 = buf + OFF_A4; float* S4 = buf + OFF_S4;
    float* A5 = buf + OFF_A5; float* S5 = buf + OFF_S5;
    float* A6 = buf + OFF_A6; float* S6 = buf + OFF_S6;
    float* A7 = buf + OFF_A7;

    // L0: pool4 (4,2,128,128)->(4,2,32,32), psp
    pool_kernel<4><<<NB * 2 * 32 * 32, 160>>>(s_in, P0, 2, 32, 32, T);
    psp_kernel<<<(NB * 2 * 32 * 32 + 127) / 128, 128>>>(P0, S0, NB * 2 * 32 * 32, TP);

    // L1: conv 5x5, 2->32, pad2, psp
    conv_kernel<2, 5, 2, 8><<<dim3(32 * 32 / 4, 4, NB), 128>>>(S0, A1, w1, 32, 32);
    psp_kernel<<<(NB * 32 * 32 * 32 + 127) / 128, 128>>>(A1, S1, NB * 32 * 32 * 32, TP);

    // L2: pool2 -> (4,32,16,16), psp
    pool_kernel<2><<<NB * 32 * 16 * 16, 160>>>(S1, A2, 32, 16, 16, TP);
    psp_kernel<<<(NB * 32 * 16 * 16 + 127) / 128, 128>>>(A2, S2, NB * 32 * 16 * 16, TP);

    // L3: conv 3x3, 32->64, pad1, psp
    conv_kernel<32, 3, 1, 8><<<dim3(16 * 16 / 4, 8, NB), 128>>>(S2, A3, w2, 16, 16);
    psp_kernel<<<(NB * 64 * 16 * 16 + 127) / 128, 128>>>(A3, S3, NB * 64 * 16 * 16, TP);

    // L4: pool2 -> (4,64,8,8), psp
    pool_kernel<2><<<NB * 64 * 8 * 8, 160>>>(S3, A4, 64, 8, 8, TP);
    psp_kernel<<<(NB * 64 * 8 * 8 + 127) / 128, 128>>>(A4, S4, NB * 64 * 8 * 8, TP);

    // L5: conv 3x3, 64->64, pad1, psp
    conv_kernel<64, 3, 1, 8><<<dim3(8 * 8 / 4, 8, NB), 128>>>(S4, A5, w3, 8, 8);
    psp_kernel<<<(NB * 64 * 8 * 8 + 127) / 128, 128>>>(A5, S5, NB * 64 * 8 * 8, TP);

    // L6: fc 4096->256, psp
    fc_kernel<8, 512><<<dim3(32, NB), 160>>>(S5, A6, w4a, 4096, 256);
    psp_kernel<<<(NB * 256 + 127) / 128, 128>>>(A6, S6, NB * 256, TP);

    // L7: fc 256->11, psp -> out (stride 300)
    fc_kernel<11, 256><<<dim3(1, NB), 160>>>(S6, A7, w4b, 256, 11);
    psp_kernel<<<1, 128>>>(A7, out, NB * 11, T);
}

// round 11
// speedup vs baseline: 3.0489x; 1.4205x over previous
#include <cuda_runtime.h>

// ---------------------------------------------------------------------------
// SLAYER SNN forward on GB300 (sm_103a), fp32, exact-order IIR.
// pool4 -> psp -> conv5x5(2->32) -> [psp+pool2+psp fused] -> conv3x3(32->64)
// -> [psp+pool2+psp fused] -> conv3x3(64->64) -> psp -> fc(4096->256, f-split)
// -> psp(sum partials) -> fc(256->11) -> psp.   N=4, T=300, stride TP=320.
// MAC kernels use fma.rn.f32x2 (2 fp32 MAC / issue slot).
// ---------------------------------------------------------------------------

#define T  300
#define TP 320
#define NB 4

#define A_SR 0.90483741803595957f   // exp(-1/10)
#define A_RF 0.36787944117144233f   // exp(-1)
#define C_SR 0.27182818284590452f   // e/10
#define C_RF -54.365636569180902f   // -2*10*e
#define THETA 10.0f

typedef unsigned long long u64;

// ---------------- scratch offsets (floats), stride TP ----------------
static const size_t OFF_P0  = 0;         // 4*2*32*32*320  = 2,621,440
static const size_t OFF_S0  = 2621440;   // 2,621,440
static const size_t OFF_A1  = 5242880;   // 4*32*32*32*320 = 41,943,040
static const size_t OFF_S2  = 47185920;  // 4*32*16*16*320 = 10,485,760
static const size_t OFF_A3  = 57671680;  // 4*64*16*16*320 = 20,971,520
static const size_t OFF_S4  = 78643200;  // 4*64*8*8*320   = 5,242,880
static const size_t OFF_A5  = 83886080;  // 5,242,880
static const size_t OFF_S5  = 89128960;  // 5,242,880
static const size_t OFF_A6P = 94371840;  // 4 partials * 4*256*320 = 1,310,720
static const size_t OFF_S6  = 95682560;  // 327,680
static const size_t OFF_A7  = 96010240;  // 4*11*320 = 14,080
// total 96,024,320 floats = 384.1 MB
__device__ float g_buf[96024320];

static const int PARTSZ = NB * 256 * TP;   // 327,680

// ---------------- f32x2 helpers ----------------
__device__ __forceinline__ u64 pack2(float a, float b) {
    u64 r; asm("mov.b64 %0, {%1, %2};" : "=l"(r) : "f"(a), "f"(b)); return r;
}
__device__ __forceinline__ void fma2(u64 &d, u64 a, u64 b) {
    asm("fma.rn.f32x2 %0, %1, %2, %0;" : "+l"(d) : "l"(a), "l"(b));
}

// ---------------- IIR step (exact op order, shared by all psp kernels) -----
__device__ __forceinline__ float iir_step(float &gp, float &hp, float &gr, float &hr,
                                          float xi)
{
    hp = __fmul_rn(A_SR, __fadd_rn(hp, gp));
    gp = __fadd_rn(__fmul_rn(A_SR, gp), xi);
    hr = __fmul_rn(A_RF, __fadd_rn(hr, gr));
    gr = __fmul_rn(A_RF, gr);
    float u = __fadd_rn(__fmul_rn(C_SR, hp), __fmul_rn(C_RF, hr));
    float s = (u >= THETA) ? 1.0f : 0.0f;
    gr = __fadd_rn(gr, s);
    return s;
}

// ---------------- sum pool (x 1.1*theta), float2 ----------------
template<int K>
__global__ __launch_bounds__(160) void pool_kernel(
    const float* __restrict__ src, float* __restrict__ dst,
    int C, int HO, int WO, int srcStride)
{
    int idx = blockIdx.x;
    int x = idx % WO; int r = idx / WO;
    int y = r % HO;   r /= HO;
    int c = r % C;    int n = r / C;
    const int WI = WO * K;
    const int HI = HO * K;
    const int t = threadIdx.x * 2;
    if (t >= T) return;
    const float* sp = src + (((((size_t)n * C + c) * HI + (size_t)y * K) * WI)
                             + (size_t)x * K) * srcStride + t;
    float sa = 0.f, sb = 0.f;
    #pragma unroll
    for (int i = 0; i < K; i++)
        #pragma unroll
        for (int j = 0; j < K; j++) {
            float2 v = *(const float2*)(sp + ((size_t)i * WI + j) * srcStride);
            sa += v.x; sb += v.y;
        }
    float2 o; o.x = 11.0f * sa; o.y = 11.0f * sb;
    *(float2*)(dst + (size_t)idx * TP + t) = o;
}

// ---------------- plain psp (+optional partial-sum input) ----------------
// Warp = 32 neurons; 32x64 (neuron x t) smem tiles, float2 coalesced IO.
template<int NPARTS>
__global__ __launch_bounds__(128) void psp_kernel(
    const float* __restrict__ src, float* __restrict__ dst,
    int nNeurons, int dstStride, int partStride)
{
    __shared__ float buf[4][32][65];
    const int warp = threadIdx.x >> 5, lane = threadIdx.x & 31;
    const int base = (blockIdx.x * 4 + warp) * 32;
    if (base >= nNeurons) return;

    float gp = 0.f, hp = 0.f, gr = 0.f, hr = 0.f;

    for (int tt = 0; tt < TP; tt += 64) {
        #pragma unroll
        for (int j = 0; j < 32; j++) {
            int ni = base + j;
            float2 v; v.x = 0.f; v.y = 0.f;
            if (ni < nNeurons && tt + 2 * lane < T) {
                const float* p = src + (size_t)ni * TP + tt + 2 * lane;
                v = *(const float2*)p;
                #pragma unroll
                for (int q = 1; q < NPARTS; q++) {
                    float2 w = *(const float2*)(p + (size_t)q * partStride);
                    v.x += w.x; v.y += w.y;
                }
            }
            buf[warp][j][2 * lane]     = v.x;
            buf[warp][j][2 * lane + 1] = v.y;
        }
        __syncwarp();
        #pragma unroll 4
        for (int k = 0; k < 64; k++) {
            float s = 0.f;
            if (tt + k < T)
                s = iir_step(gp, hp, gr, hr, buf[warp][lane][k]);
            buf[warp][lane][k] = s;
        }
        __syncwarp();
        #pragma unroll
        for (int j = 0; j < 32; j++) {
            int ni = base + j;
            if (ni < nNeurons && tt + 2 * lane < dstStride) {
                float2 v;
                v.x = buf[warp][j][2 * lane];
                v.y = buf[warp][j][2 * lane + 1];
                *(float2*)(dst + (size_t)ni * dstStride + tt + 2 * lane) = v;
            }
        }
        __syncwarp();
    }
}

// ---------------- fused psp -> pool2 -> psp ----------------
// Warp = 8 pooled pixels x 4 (2x2) sources = 32 source neurons.
// IIR1 on sources (lane = source), spikes pooled via 2 butterfly shuffles,
// IIR2 on pooled neurons inline. Writes pooled spikes only.
__global__ __launch_bounds__(128) void psppool_kernel(
    const float* __restrict__ src, float* __restrict__ dst,
    int C, int HO, int WO)
{
    __shared__ float bufS[4][32][65];
    __shared__ float bufP[4][8][65];
    const int warp = threadIdx.x >> 5, lane = threadIdx.x & 31;
    const int pb = (blockIdx.x * 4 + warp) * 8;     // pooled base of this warp

    // lane's own source row (source grid is 2H x 2W), shuffled to peers in load
    int pi = pb + (lane >> 2);
    int x = pi % WO; int rr = pi / WO;
    int y = rr % HO; rr /= HO;
    int c = rr % C;  int n = rr / C;
    const int HI = 2 * HO, WI = 2 * WO;
    int srow = ((n * C + c) * HI + 2 * y + ((lane >> 1) & 1)) * WI
               + 2 * x + (lane & 1);

    float gp = 0.f, hp = 0.f, gr = 0.f, hr = 0.f;       // source IIR
    float gp2 = 0.f, hp2 = 0.f, gr2 = 0.f, hr2 = 0.f;   // pooled IIR

    for (int tt = 0; tt < TP; tt += 64) {
        #pragma unroll
        for (int j = 0; j < 32; j++) {
            int r = __shfl_sync(0xffffffffu, srow, j);
            float2 v = *(const float2*)(src + (size_t)r * TP + tt + 2 * lane);
            bufS[warp][j][2 * lane]     = v.x;
            bufS[warp][j][2 * lane + 1] = v.y;
        }
        __syncwarp();
        #pragma unroll 4
        for (int k = 0; k < 64; k++) {
            float s2 = 0.f;
            if (tt + k < T) {
                float s = iir_step(gp, hp, gr, hr, bufS[warp][lane][k]);
                float sm = s + __shfl_xor_sync(0xffffffffu, s, 1);
                sm = sm + __shfl_xor_sync(0xffffffffu, sm, 2);
                s2 = iir_step(gp2, hp2, gr2, hr2, __fmul_rn(11.0f, sm));
            }
            if ((lane & 3) == 0) bufP[warp][lane >> 2][k] = s2;
        }
        __syncwarp();
        #pragma unroll
        for (int j2 = 0; j2 < 8; j2++) {
            float2 v;
            v.x = bufP[warp][j2][2 * lane];
            v.y = bufP[warp][j2][2 * lane + 1];
            *(float2*)(dst + (size_t)(pb + j2) * TP + tt + 2 * lane) = v;
        }
        __syncwarp();
    }
}

// ---------------- per-timestep 2D conv, f32x2 packed ----------------
// Block = 4 warps = 2 adjacent pixels x 2 ocg halves (input shared via L1).
// Warp: lane covers t = 2*lane + 64*j (j=0..4), G ocs in registers.
template<int IC, int K, int PAD, int G>
__global__ __launch_bounds__(128) void conv_kernel(
    const float* __restrict__ src, float* __restrict__ dst,
    const float* __restrict__ w, int H, int W)
{
    constexpr int KK = K * K;
    constexpr int ICKK = IC * KK;
    __shared__ u64 swd[2 * G * ICKK];

    const int lane = threadIdx.x & 31;
    const int warp = threadIdx.x >> 5;
    const int n  = blockIdx.z;
    const int OC = gridDim.y * 2 * G;

    for (int i = threadIdx.x; i < 2 * G * ICKK; i += 128) {
        float v = w[(size_t)blockIdx.y * 2 * G * ICKK + i];
        swd[i] = pack2(v, v);
    }
    __syncthreads();

    const int pixel = blockIdx.x * 2 + (warp & 1);
    const int ocg   = blockIdx.y * 2 + (warp >> 1);
    const u64* wslice = swd + (size_t)(warp >> 1) * G * ICKK;
    const int x = pixel % W, y = pixel / W;

    u64 acc[5][G];
    #pragma unroll
    for (int j = 0; j < 5; j++)
        #pragma unroll
        for (int g = 0; g < G; g++) acc[j][g] = 0ull;

    const float* sb = src + ((size_t)n * IC * H * W) * TP + lane * 2;

    #pragma unroll
    for (int ky = 0; ky < K; ky++) {
        int iy = y + ky - PAD;
        if (iy < 0 || iy >= H) continue;
        #pragma unroll
        for (int kx = 0; kx < K; kx++) {
            int ix = x + kx - PAD;
            if (ix < 0 || ix >= W) continue;
            const float* tap = sb + (size_t)(iy * W + ix) * TP;
            #pragma unroll (IC <= 4 ? IC : 2)
            for (int ic = 0; ic < IC; ic++) {
                const float* p = tap + (size_t)ic * H * W * TP;
                u64 v[5];
                #pragma unroll
                for (int j = 0; j < 5; j++)
                    v[j] = *(const u64*)(p + 64 * j);
                #pragma unroll
                for (int g = 0; g < G; g++) {
                    u64 wv = wslice[g * ICKK + ic * KK + ky * K + kx];
                    #pragma unroll
                    for (int j = 0; j < 5; j++)
                        fma2(acc[j][g], v[j], wv);
                }
            }
        }
    }

    float* dp = dst + ((size_t)(n * OC + ocg * G) * H * W + pixel) * TP + lane * 2;
    #pragma unroll
    for (int g = 0; g < G; g++)
        #pragma unroll
        for (int j = 0; j < 5; j++)
            *(u64*)(dp + (size_t)g * H * W * TP + 64 * j) = acc[j][g];
}

// ---------------- fully connected, f32x2 packed, optional f-split ----------
// grid (OC/G, N, FSPLITS); block 160 = 5 warps (t chunks of 64).
template<int G, int CF>
__global__ __launch_bounds__(160) void fc_kernel(
    const float* __restrict__ src, float* __restrict__ dst,
    const float* __restrict__ w, int INF, int OC, int fLen, int partStride)
{
    __shared__ u64 swd[G * CF];
    const int lane = threadIdx.x & 31, warp = threadIdx.x >> 5;
    const int og = blockIdx.x, n = blockIdx.y, fs = blockIdx.z;
    const int fbase = fs * fLen;
    const int tbase = warp * 64 + lane * 2;

    u64 acc[G];
    #pragma unroll
    for (int g = 0; g < G; g++) acc[g] = 0ull;

    for (int f0 = fbase; f0 < fbase + fLen; f0 += CF) {
        __syncthreads();
        for (int i = threadIdx.x; i < G * CF; i += 160) {
            float v = w[(size_t)(og * G + i / CF) * INF + f0 + (i % CF)];
            swd[i] = pack2(v, v);
        }
        __syncthreads();
        const float* sp = src + ((size_t)n * INF + f0) * TP + tbase;
        for (int f = 0; f < CF; f++) {
            u64 v = *(const u64*)(sp + (size_t)f * TP);
            #pragma unroll
            for (int g = 0; g < G; g++)
                fma2(acc[g], v, swd[g * CF + f]);
        }
    }

    float* dp = dst + (size_t)fs * partStride
                    + ((size_t)n * OC + og * G) * TP + tbase;
    #pragma unroll
    for (int g = 0; g < G; g++)
        *(u64*)(dp + (size_t)g * TP) = acc[g];
}

// ---------------------------------------------------------------------------
extern "C" void kernel_launch(void* const* d_in, const int* in_sizes, int n_in,
                              void* d_out, int out_size)
{
    const float* s_in = (const float*)d_in[0];   // (4,2,128,128,300)
    const float* w1   = (const float*)d_in[1];   // (32,2,5,5)
    const float* w2   = (const float*)d_in[2];   // (64,32,3,3)
    const float* w3   = (const float*)d_in[3];   // (64,64,3,3)
    const float* w4a  = (const float*)d_in[4];   // (256,4096)
    const float* w4b  = (const float*)d_in[5];   // (11,256)
    float* out = (float*)d_out;                  // (4,11,300)

    float* buf = nullptr;
    cudaGetSymbolAddress((void**)&buf, g_buf);

    float* P0  = buf + OFF_P0;  float* S0 = buf + OFF_S0;
    float* A1  = buf + OFF_A1;  float* S2 = buf + OFF_S2;
    float* A3  = buf + OFF_A3;  float* S4 = buf + OFF_S4;
    float* A5  = buf + OFF_A5;  float* S5 = buf + OFF_S5;
    float* A6P = buf + OFF_A6P; float* S6 = buf + OFF_S6;
    float* A7  = buf + OFF_A7;

    // L0: pool4 (4,2,128,128)->(4,2,32,32), psp
    pool_kernel<4><<<NB * 2 * 32 * 32, 160>>>(s_in, P0, 2, 32, 32, T);
    psp_kernel<1><<<64, 128>>>(P0, S0, NB * 2 * 32 * 32, TP, 0);

    // L1: conv 5x5, 2->32, pad2 ; fused psp+pool2+psp -> S2 (4,32,16,16)
    conv_kernel<2, 5, 2, 8><<<dim3(512, 2, NB), 128>>>(S0, A1, w1, 32, 32);
    psppool_kernel<<<1024, 128>>>(A1, S2, 32, 16, 16);

    // L3: conv 3x3, 32->64, pad1 ; fused psp+pool2+psp -> S4 (4,64,8,8)
    conv_kernel<32, 3, 1, 8><<<dim3(128, 4, NB), 128>>>(S2, A3, w2, 16, 16);
    psppool_kernel<<<512, 128>>>(A3, S4, 64, 8, 8);

    // L5: conv 3x3, 64->64, pad1 ; psp
    conv_kernel<64, 3, 1, 8><<<dim3(32, 4, NB), 128>>>(S4, A5, w3, 8, 8);
    psp_kernel<1><<<32, 128>>>(A5, S5, NB * 64 * 8 * 8, TP, 0);

    // L6: fc 4096->256 split over f into 4 partials; psp sums partials
    fc_kernel<8, 512><<<dim3(32, NB, 4), 160>>>(S5, A6P, w4a, 4096, 256, 1024, PARTSZ);
    psp_kernel<4><<<8, 128>>>(A6P, S6, NB * 256, TP, PARTSZ);

    // L7: fc 256->11 ; psp -> out (stride 300)
    fc_kernel<11, 256><<<dim3(1, NB, 1), 160>>>(S6, A7, w4b, 256, 11, 256, 0);
    psp_kernel<1><<<1, 128>>>(A7, out, NB * 11, T, 0);
}